// round 5
// baseline (speedup 1.0000x reference)
#include <cuda_runtime.h>
#include <cstdint>

// NoiseMixModule: out = mask*A + (1-mask)*B, mask from double-argsort ranks of u.
//
// R5 = R4 inner code with finer CTA granularity for wave balance:
//   128 threads (4 warps) per block, 128 rows/warp -> 512 rows/block,
//   8192 blocks. regs ~44 -> 11 blocks/SM resident, n_conc = 1628,
//   8192/1628 = 5.03 waves (vs 5.53 at R4's 1024-row blocks).
//
//   phase 1: stage u slice into warp's smem strip (coalesced float4)
//   phase 2: SWAR nibble rank counts -> mask word per row in smem
//   phase 3: batched A/B blend, groups of 4 then 3 k's (MLP_p1 = 8)

static constexpr int THREADS        = 128;
static constexpr int WARPS          = THREADS / 32;            // 4
static constexpr int ROWS_PER_WARP  = 128;
static constexpr int F4_PER_WARP    = ROWS_PER_WARP * 7 / 4;   // 224
static constexpr int ROWS_PER_BLOCK = ROWS_PER_WARP * WARPS;   // 512
static constexpr int F4_PER_BLOCK   = F4_PER_WARP * WARPS;     // 896

__global__ __launch_bounds__(THREADS)
void noisemix_kernel(const float4* __restrict__ A,
                     const float4* __restrict__ B,
                     const float*  __restrict__ LAM,
                     const float4* __restrict__ U,
                     float4* __restrict__ OUT)
{
    __shared__ float    su[ROWS_PER_BLOCK * 7];     // 14 KB, per-warp strips
    __shared__ uint32_t smask[ROWS_PER_BLOCK];      //  2 KB, SWAR mask words

    const int warp = threadIdx.x >> 5;
    const int lane = threadIdx.x & 31;

    float*    suw    = su    + warp * ROWS_PER_WARP * 7;
    uint32_t* smaskw = smask + warp * ROWS_PER_WARP;

    const long wbase4   = (long)blockIdx.x * F4_PER_BLOCK + warp * F4_PER_WARP;
    const long wrowbase = (long)blockIdx.x * ROWS_PER_BLOCK + warp * ROWS_PER_WARP;

    // ---- phase 1: coalesced stage of this warp's u ----
    float4* suw4 = reinterpret_cast<float4*>(suw);
#pragma unroll
    for (int k = 0; k < 7; k++) {
        suw4[k * 32 + lane] = U[wbase4 + k * 32 + lane];
    }
    __syncwarp();

    // ---- phase 2: SWAR rank counts, 4 rows per lane ----
    // stable double-argsort rank: pair (a<b): u[a] <= u[b] -> b gains a
    // predecessor, else a does. cnt_d lives in nibble d of acc.
    // mask bit d = (cnt_d >= nz) = bit3 of nibble d of acc + (8-nz)*0x01111111.
#pragma unroll
    for (int j = 0; j < 4; j++) {
        const int row = lane + j * 32;           // stride-7 LDS: conflict-free
        float uu[7];
#pragma unroll
        for (int d = 0; d < 7; d++) uu[d] = suw[row * 7 + d];

        const float lamv = LAM[wrowbase + row];  // coalesced 4B/lane
        const int   nz   = (int)floorf(7.0f * (1.0f - lamv));

        uint32_t acc = 0;
#pragma unroll
        for (int a = 0; a < 7; a++)
#pragma unroll
            for (int b = a + 1; b < 7; b++)
                acc += (uu[a] <= uu[b]) ? (1u << (4 * b)) : (1u << (4 * a));

        smaskw[row] = acc + (uint32_t)(8 - nz) * 0x01111111u;
    }
    __syncwarp();

    // ---- phase 3: batched A/B stream + blend ----
    // group 1: k = 0..3 (8 float4 in flight), group 2: k = 4..6 (6 float4)
#pragma unroll
    for (int g = 0; g < 2; g++) {
        const int k0 = (g == 0) ? 0 : 4;
        const int kn = (g == 0) ? 4 : 3;

        float4 a[4], b[4];
#pragma unroll
        for (int k = 0; k < 4; k++) {
            if (k < kn) {
                const long idx4 = wbase4 + (k0 + k) * 32 + lane;
                a[k] = A[idx4];
                b[k] = B[idx4];
            }
        }

#pragma unroll
        for (int k = 0; k < 4; k++) {
            if (k < kn) {
                int le  = ((k0 + k) * 32 + lane) * 4;   // element idx in warp tile
                int row = le / 7;
                int d   = le - row * 7;

                uint32_t m = smaskw[row];
                float4 o;
                o.x = (m >> (4 * d + 3)) & 1u ? a[k].x : b[k].x;
                d++; if (d == 7) { d = 0; row++; m = smaskw[row]; }
                o.y = (m >> (4 * d + 3)) & 1u ? a[k].y : b[k].y;
                d++; if (d == 7) { d = 0; row++; m = smaskw[row]; }
                o.z = (m >> (4 * d + 3)) & 1u ? a[k].z : b[k].z;
                d++; if (d == 7) { d = 0; row++; m = smaskw[row]; }
                o.w = (m >> (4 * d + 3)) & 1u ? a[k].w : b[k].w;

                OUT[wbase4 + (k0 + k) * 32 + lane] = o;
            }
        }
    }
}

extern "C" void kernel_launch(void* const* d_in, const int* in_sizes, int n_in,
                              void* d_out, int out_size)
{
    const float4* A   = (const float4*)d_in[0];   // noise_A [B,7]
    const float4* Bp  = (const float4*)d_in[1];   // noise_B [B,7]
    const float*  LAM = (const float*)d_in[2];    // lam [B]
    const float4* U   = (const float4*)d_in[3];   // u [B,7]
    float4* OUT = (float4*)d_out;

    const int Brows  = in_sizes[2];                // 4194304
    const int blocks = Brows / ROWS_PER_BLOCK;     // 8192

    noisemix_kernel<<<blocks, THREADS>>>(A, Bp, LAM, U, OUT);
}